// round 12
// baseline (speedup 1.0000x reference)
#include <cuda_runtime.h>
#include <cuda_fp16.h>
#include <cstdint>

#define RR 12
#define LL 1728
#define CC 768
#define HD 64
#define NH 12
#define BB 4
#define BM 96            // query rows per CTA (exact: 1728 = 96*18)
#define BN 64
#define NITER (LL / BN)  // 27
#define NT 96            // threads per CTA (3 warps)
#define QSCALE (0.125f * 1.4426950408889634f)  // hd^-0.5 * log2(e)
#define OSTR 68
#define QB   (BM * 128)            // 12288 (swizzled, no padding)
#define TILE (BN * 128)            // 8192
#define SMEM_TOTAL (QB + 4 * TILE) // 45056 -> 5 CTAs/SM

#define BLC ((size_t)BB * LL * CC)

__device__ float  g_lepe[BLC];
__device__ __half g_qh[BLC];
__device__ __half g_kh[BLC];
__device__ __half g_vh[BLC];

// swizzled smem address: 128B rows, 16B chunks, chunk ^= row&7
__device__ __forceinline__ uint32_t swz(uint32_t base, int row, int chunk) {
    return base + ((uint32_t)row << 7) + (((uint32_t)(chunk ^ (row & 7))) << 4);
}

// ---------------------------------------------------------------------------
// Convert Q (scaled by hd^-0.5 * log2e) and K to fp16.
// ---------------------------------------------------------------------------
__global__ void __launch_bounds__(256) convert_qk(const float* __restrict__ qkv) {
    const size_t i = ((size_t)blockIdx.x * 256 + threadIdx.x) * 8;
    const float4 a = *(const float4*)(qkv + i);
    const float4 b = *(const float4*)(qkv + i + 4);
    __half2 q0 = __floats2half2_rn(a.x * QSCALE, a.y * QSCALE);
    __half2 q1 = __floats2half2_rn(a.z * QSCALE, a.w * QSCALE);
    __half2 q2 = __floats2half2_rn(b.x * QSCALE, b.y * QSCALE);
    __half2 q3 = __floats2half2_rn(b.z * QSCALE, b.w * QSCALE);
    *(uint4*)(g_qh + i) = make_uint4(*(uint32_t*)&q0, *(uint32_t*)&q1,
                                     *(uint32_t*)&q2, *(uint32_t*)&q3);
    const float4 c = *(const float4*)(qkv + BLC + i);
    const float4 d = *(const float4*)(qkv + BLC + i + 4);
    __half2 k0 = __floats2half2_rn(c.x, c.y);
    __half2 k1 = __floats2half2_rn(c.z, c.w);
    __half2 k2 = __floats2half2_rn(d.x, d.y);
    __half2 k3 = __floats2half2_rn(d.z, d.w);
    *(uint4*)(g_kh + i) = make_uint4(*(uint32_t*)&k0, *(uint32_t*)&k1,
                                     *(uint32_t*)&k2, *(uint32_t*)&k3);
}

// ---------------------------------------------------------------------------
// LePE depthwise 3x3x3 conv, sliding-window along x; also emits fp16 V.
// ---------------------------------------------------------------------------
__global__ void __launch_bounds__(256) lepe_kernel(const float* __restrict__ v,
                                                   const float* __restrict__ w,
                                                   const float* __restrict__ bias) {
    __shared__ float ws[256 * 27];
    const int bx   = blockIdx.x;
    const int cseg = bx % 3;
    const int y    = (bx / 3) % RR;
    const int z    = bx / (3 * RR);
    const int b    = blockIdx.y;
    const int c0   = cseg * 256;
    const int tid  = threadIdx.x;
    const int c    = c0 + tid;

    for (int i = tid; i < 256 * 27; i += 256) ws[i] = w[c0 * 27 + i];
    __syncthreads();
    float wr[27];
    #pragma unroll
    for (int i = 0; i < 27; i++) wr[i] = ws[tid * 27 + i];
    const float bv = bias[c];

    size_t nb[9];
    bool   nv[9];
    #pragma unroll
    for (int dz = 0; dz < 3; dz++) {
        #pragma unroll
        for (int dy = 0; dy < 3; dy++) {
            const int zz = z + dz - 1, yy = y + dy - 1;
            const bool ok = ((unsigned)zz < RR) && ((unsigned)yy < RR);
            nv[dz * 3 + dy] = ok;
            nb[dz * 3 + dy] = ok ? (((size_t)b * LL + (zz * RR + yy) * RR) * CC + c) : 0;
        }
    }
    const size_t ob = ((size_t)b * LL + (z * RR + y) * RR) * CC + c;

    float A = bv, Bc = bv;
    #pragma unroll
    for (int xx = 0; xx < RR; xx++) {
        float t0 = 0.f, t1 = 0.f, t2 = 0.f;
        #pragma unroll
        for (int n = 0; n < 9; n++) {
            if (nv[n]) {
                const float vv = v[nb[n] + (size_t)xx * CC];
                if (n == 4) g_vh[nb[4] + (size_t)xx * CC] = __float2half_rn(vv);
                t0 += wr[n * 3 + 0] * vv;
                t1 += wr[n * 3 + 1] * vv;
                t2 += wr[n * 3 + 2] * vv;
            }
        }
        if (xx > 0) g_lepe[ob + (size_t)(xx - 1) * CC] = A + t2;
        A  = Bc + t1;
        Bc = bv + t0;
    }
    g_lepe[ob + (size_t)(RR - 1) * CC] = A;
}

// ---------------------------------------------------------------------------
// mma / cp.async helpers
// ---------------------------------------------------------------------------
__device__ __forceinline__ uint32_t smem_u32(const void* p) {
    uint32_t a;
    asm("{ .reg .u64 t; cvta.to.shared.u64 t, %1; cvt.u32.u64 %0, t; }" : "=r"(a) : "l"(p));
    return a;
}
__device__ __forceinline__ void ldsm4(uint32_t* r, uint32_t addr) {
    asm volatile("ldmatrix.sync.aligned.m8n8.x4.shared.b16 {%0,%1,%2,%3}, [%4];"
                 : "=r"(r[0]), "=r"(r[1]), "=r"(r[2]), "=r"(r[3]) : "r"(addr));
}
__device__ __forceinline__ void ldsm4t(uint32_t* r, uint32_t addr) {
    asm volatile("ldmatrix.sync.aligned.m8n8.x4.trans.shared.b16 {%0,%1,%2,%3}, [%4];"
                 : "=r"(r[0]), "=r"(r[1]), "=r"(r[2]), "=r"(r[3]) : "r"(addr));
}
__device__ __forceinline__ void mma16816(float* d, const uint32_t* a, const uint32_t* b) {
    asm volatile("mma.sync.aligned.m16n8k16.row.col.f32.f16.f16.f32 "
                 "{%0,%1,%2,%3}, {%4,%5,%6,%7}, {%8,%9}, {%0,%1,%2,%3};"
                 : "+f"(d[0]), "+f"(d[1]), "+f"(d[2]), "+f"(d[3])
                 : "r"(a[0]), "r"(a[1]), "r"(a[2]), "r"(a[3]), "r"(b[0]), "r"(b[1]));
}
__device__ __forceinline__ uint32_t exp2_pack(float lo, float hi) {
    __half2 h = __floats2half2_rn(lo, hi);
    uint32_t r;
    asm("ex2.approx.f16x2 %0, %1;" : "=r"(r) : "r"(*(uint32_t*)&h));
    return r;
}
__device__ __forceinline__ void cpa16(uint32_t dst, const void* src) {
    asm volatile("cp.async.cg.shared.global [%0], [%1], 16;" :: "r"(dst), "l"(src));
}
#define CPA_COMMIT() asm volatile("cp.async.commit_group;" ::: "memory")
#define CPA_WAIT(n)  asm volatile("cp.async.wait_group %0;" :: "n"(n) : "memory")

// stage one 64-key fp16 K/V tile via cp.async into swizzled layout
__device__ __forceinline__ void stage_kv(uint32_t kd, uint32_t vd,
                                         const __half* __restrict__ kh,
                                         const __half* __restrict__ vh,
                                         int l0, int tid) {
    for (int i = tid; i < 512; i += NT) {
        const int r = i >> 3, ch = i & 7;
        const size_t g = (size_t)(l0 + r) * CC + ch * 8;
        cpa16(swz(kd, r, ch), kh + g);
        cpa16(swz(vd, r, ch), vh + g);
    }
}

// ---------------------------------------------------------------------------
// fp16 HMMA flash attention. CTA = 96 threads = 3 independent warps x 32 rows.
// Swizzled smem (no padding) -> 45KB -> 5 CTAs/SM. 16-key subtile softmax
// keeps live registers ~136.
// ---------------------------------------------------------------------------
__global__ void __launch_bounds__(NT, 5) attn_kernel(float* __restrict__ out) {
    extern __shared__ __align__(128) char dsm[];
    __shared__ float Ls[BM];
    float* Os = (float*)dsm;

    const int tid  = threadIdx.x;
    const int lane = tid & 31;
    const int wm   = tid >> 5;    // warp = M third (32 rows)
    const int b    = blockIdx.y / NH;
    const int h    = blockIdx.y % NH;
    const int row0 = blockIdx.x * BM;

    const __half* qh = g_qh + (size_t)b * LL * CC + h * HD;
    const __half* kh = g_kh + (size_t)b * LL * CC + h * HD;
    const __half* vh = g_vh + (size_t)b * LL * CC + h * HD;

    const uint32_t qsm = smem_u32(dsm);
    const uint32_t ksm = qsm + QB;            // 2 K buffers
    const uint32_t vsm = qsm + QB + 2 * TILE; // 2 V buffers

    // --- prologue: async-stage Q (768 chunks), tile0 ---
    #pragma unroll
    for (int p = 0; p < 8; p++) {
        const int i = tid + p * NT;
        const int r = i >> 3, ch = i & 7;
        cpa16(swz(qsm, r, ch), qh + (size_t)(row0 + r) * CC + ch * 8);
    }
    stage_kv(ksm, vsm, kh, vh, 0, tid);
    CPA_COMMIT();
    CPA_WAIT(0);
    __syncthreads();

    // fragment address permutations
    const int arow = lane & 15;                           // A (Q)
    const int acc8 = lane >> 4;                           // A chunk half (0/1)
    const int frow = ((lane >> 4) & 1) * 8 + (lane & 7);  // B (K)
    const int fcc8 = (lane >> 3) & 1;
    const int trow = lane & 15;                           // trans B (V)
    const int tcc8 = (lane >> 4) & 1;

    uint32_t aq[2][4][4];
    #pragma unroll
    for (int mt = 0; mt < 2; mt++) {
        const int R = wm * 32 + mt * 16 + arow;
        #pragma unroll
        for (int kc = 0; kc < 4; kc++)
            ldsm4(aq[mt][kc], swz(qsm, R, kc * 2 + acc8));
    }

    float oacc[2][8][4];
    #pragma unroll
    for (int mt = 0; mt < 2; mt++)
        #pragma unroll
        for (int j = 0; j < 8; j++)
            #pragma unroll
            for (int e = 0; e < 4; e++) oacc[mt][j][e] = 0.f;
    float lsA[2] = {0.f, 0.f}, lsB[2] = {0.f, 0.f};

    for (int it = 0; it < NITER; it++) {
        const uint32_t kbase = ksm + (uint32_t)(it & 1) * TILE;
        const uint32_t vbase = vsm + (uint32_t)(it & 1) * TILE;

        if (it + 1 < NITER)
            stage_kv(ksm + ((it + 1) & 1) * TILE, vsm + ((it + 1) & 1) * TILE,
                     kh, vh, (it + 1) * BN, tid);
        CPA_COMMIT();

        // four 16-key subtiles (minimal live registers)
        #pragma unroll
        for (int s4 = 0; s4 < 4; s4++) {
            const int krow = s4 * 16;

            // --- S = Q K^T for 16 keys ---
            float sacc[2][2][4];
            #pragma unroll
            for (int mt = 0; mt < 2; mt++)
                #pragma unroll
                for (int j = 0; j < 2; j++)
                    #pragma unroll
                    for (int e = 0; e < 4; e++) sacc[mt][j][e] = 0.f;

            #pragma unroll
            for (int ks = 0; ks < 4; ks++) {
                uint32_t kb[4];
                ldsm4(kb, swz(kbase, krow + frow, ks * 2 + fcc8));
                #pragma unroll
                for (int mt = 0; mt < 2; mt++) {
                    mma16816(sacc[mt][0], aq[mt][ks], kb);
                    mma16816(sacc[mt][1], aq[mt][ks], kb + 2);
                }
            }

            // --- softmax: p = 2^s fp16x2 (scores already log2-domain) ---
            uint32_t pf[2][4];
            #pragma unroll
            for (int mt = 0; mt < 2; mt++) {
                const uint32_t p0 = exp2_pack(sacc[mt][0][0], sacc[mt][0][1]);
                const uint32_t p1 = exp2_pack(sacc[mt][0][2], sacc[mt][0][3]);
                const uint32_t p2 = exp2_pack(sacc[mt][1][0], sacc[mt][1][1]);
                const uint32_t p3 = exp2_pack(sacc[mt][1][2], sacc[mt][1][3]);
                pf[mt][0] = p0; pf[mt][1] = p1; pf[mt][2] = p2; pf[mt][3] = p3;
                __half2 hA = __hadd2(*(const __half2*)&p0, *(const __half2*)&p2);
                __half2 hB = __hadd2(*(const __half2*)&p1, *(const __half2*)&p3);
                const float2 fA = __half22float2(hA);
                const float2 fB = __half22float2(hB);
                lsA[mt] += fA.x + fA.y;
                lsB[mt] += fB.x + fB.y;
            }

            // --- O += P V ---
            #pragma unroll
            for (int j2 = 0; j2 < 4; j2++) {
                uint32_t vb[4];
                ldsm4t(vb, swz(vbase, krow + trow, j2 * 2 + tcc8));
                #pragma unroll
                for (int mt = 0; mt < 2; mt++) {
                    mma16816(oacc[mt][2 * j2],     pf[mt], vb);
                    mma16816(oacc[mt][2 * j2 + 1], pf[mt], vb + 2);
                }
            }
        }

        CPA_WAIT(0);
        __syncthreads();
    }

    // --- row sums (quad reduce, rows private to warp) ---
    #pragma unroll
    for (int mt = 0; mt < 2; mt++) {
        lsA[mt] += __shfl_xor_sync(0xFFFFFFFFu, lsA[mt], 1);
        lsA[mt] += __shfl_xor_sync(0xFFFFFFFFu, lsA[mt], 2);
        lsB[mt] += __shfl_xor_sync(0xFFFFFFFFu, lsB[mt], 1);
        lsB[mt] += __shfl_xor_sync(0xFFFFFFFFu, lsB[mt], 2);
    }
    if ((lane & 3) == 0) {
        #pragma unroll
        for (int mt = 0; mt < 2; mt++) {
            const int r = wm * 32 + mt * 16 + (lane >> 2);
            Ls[r]     = lsA[mt];
            Ls[r + 8] = lsB[mt];
        }
    }
    __syncthreads();   // done with K/V smem; Os may overlay

    // --- stage O through smem ---
    const int rb = wm * 32 + (lane >> 2);
    const int cq = (lane & 3) * 2;
    #pragma unroll
    for (int mt = 0; mt < 2; mt++)
        #pragma unroll
        for (int j = 0; j < 8; j++) {
            *(float2*)(Os + (rb + mt * 16) * OSTR + j * 8 + cq) =
                make_float2(oacc[mt][j][0], oacc[mt][j][1]);
            *(float2*)(Os + (rb + mt * 16 + 8) * OSTR + j * 8 + cq) =
                make_float2(oacc[mt][j][2], oacc[mt][j][3]);
        }
    __syncthreads();

    // --- coalesced store: O/lsum + lepe ---
    #pragma unroll
    for (int p = 0; p < 16; p++) {
        const int i = tid + p * NT;
        const int rr = i >> 4, f4 = i & 15;
        const float inv = 1.f / Ls[rr];
        const size_t g = (size_t)b * LL * CC + (size_t)(row0 + rr) * CC + h * HD + f4 * 4;
        float4 ov = *(float4*)(Os + rr * OSTR + f4 * 4);
        const float4 l4 = *(const float4*)(g_lepe + g);
        ov.x = ov.x * inv + l4.x;
        ov.y = ov.y * inv + l4.y;
        ov.z = ov.z * inv + l4.z;
        ov.w = ov.w * inv + l4.w;
        *(float4*)(out + g) = ov;
    }
}

extern "C" void kernel_launch(void* const* d_in, const int* in_sizes, int n_in,
                              void* d_out, int out_size) {
    const float* qkv  = (const float*)d_in[0];
    const float* w    = (const float*)d_in[1];
    const float* bias = (const float*)d_in[2];
    float* out = (float*)d_out;

    cudaFuncSetAttribute(attn_kernel, cudaFuncAttributeMaxDynamicSharedMemorySize,
                         SMEM_TOTAL);

    convert_qk<<<(int)(BLC / 8 / 256), 256>>>(qkv);

    const size_t VOFF = 2 * BLC;
    dim3 lgrid(3 * RR * RR, BB);
    lepe_kernel<<<lgrid, 256>>>(qkv + VOFF, w, bias);

    dim3 grid(LL / BM, BB * NH);
    attn_kernel<<<grid, NT, SMEM_TOTAL>>>(out);
}

// round 13
// speedup vs baseline: 1.4064x; 1.4064x over previous
#include <cuda_runtime.h>
#include <cuda_fp16.h>
#include <cstdint>

#define RR 12
#define LL 1728
#define CC 768
#define HD 64
#define NH 12
#define BB 4
#define BM 96
#define BN 64
#define NITER (LL / BN)
#define NT 96
#define QSCALE (0.125f * 1.4426950408889634f)
#define QSTR 72
#define OSTR 68
#define QB   (BM * QSTR * 2)
#define TILE (BN * QSTR * 2)
#define SMEM_TOTAL (QB + 4 * TILE)

#define BLC ((size_t)BB * LL * CC)

__device__ float  g_lepe[BLC];
__device__ __half g_qh[BLC];
__device__ __half g_kh[BLC];
__device__ __half g_vh[BLC];

__global__ void __launch_bounds__(256) convert_qk(const float* __restrict__ qkv) {
    const size_t i = ((size_t)blockIdx.x * 256 + threadIdx.x) * 8;
    const float4 a = *(const float4*)(qkv + i);
    const float4 b = *(const float4*)(qkv + i + 4);
    __half2 q0 = __floats2half2_rn(a.x * QSCALE, a.y * QSCALE);
    __half2 q1 = __floats2half2_rn(a.z * QSCALE, a.w * QSCALE);
    __half2 q2 = __floats2half2_rn(b.x * QSCALE, b.y * QSCALE);
    __half2 q3 = __floats2half2_rn(b.z * QSCALE, b.w * QSCALE);
    *(uint4*)(g_qh + i) = make_uint4(*(uint32_t*)&q0, *(uint32_t*)&q1,
                                     *(uint32_t*)&q2, *(uint32_t*)&q3);
    const float4 c = *(const float4*)(qkv + BLC + i);
    const float4 d = *(const float4*)(qkv + BLC + i + 4);
    __half2 k0 = __floats2half2_rn(c.x, c.y);
    __half2 k1 = __floats2half2_rn(c.z, c.w);
    __half2 k2 = __floats2half2_rn(d.x, d.y);
    __half2 k3 = __floats2half2_rn(d.z, d.w);
    *(uint4*)(g_kh + i) = make_uint4(*(uint32_t*)&k0, *(uint32_t*)&k1,
                                     *(uint32_t*)&k2, *(uint32_t*)&k3);
}

// ---------------------------------------------------------------------------
// LePE depthwise 3x3x3, rolling-y. Block = (b, z, cseg); y-front reads only
// rows (z-1,z,z+1) at y: 3x read amplification vs 9x. out[x] = w0*v[x-1]
// + w1*v[x] + w2*v[x+1]; same for y (t0->out[y+1], t1->out[y], t2->out[y-1]).
// fp16 V emitted on dz==1 (zz==z) row, exactly once per element.
// ---------------------------------------------------------------------------
__global__ void __launch_bounds__(256) lepe_kernel(const float* __restrict__ v,
                                                   const float* __restrict__ w,
                                                   const float* __restrict__ bias) {
    __shared__ float ws[256 * 27];
    const int bx   = blockIdx.x;          // 0..35
    const int cseg = bx % 3;
    const int z    = bx / 3;
    const int b    = blockIdx.y;
    const int c0   = cseg * 256;
    const int tid  = threadIdx.x;
    const int c    = c0 + tid;

    for (int i = tid; i < 256 * 27; i += 256) ws[i] = w[c0 * 27 + i];
    __syncthreads();
    float wr[27];
    #pragma unroll
    for (int i = 0; i < 27; i++) wr[i] = ws[tid * 27 + i];
    const float bv = bias[c];

    const size_t zb = ((size_t)b * LL + (size_t)z * RR * RR) * CC + c;
    const size_t zstep = (size_t)RR * RR * CC;

    float A[RR], Bc[RR];
    #pragma unroll
    for (int x = 0; x < RR; x++) { A[x] = bv; Bc[x] = bv; }

    for (int yy = 0; yy < RR; yy++) {
        float t0[RR], t1[RR], t2[RR];
        #pragma unroll
        for (int x = 0; x < RR; x++) { t0[x] = 0.f; t1[x] = 0.f; t2[x] = 0.f; }

        #pragma unroll
        for (int dz = 0; dz < 3; dz++) {
            const int zz = z + dz - 1;
            if ((unsigned)zz >= RR) continue;
            const size_t rowb = zb + (size_t)(dz - 1) * zstep + (size_t)(yy * RR) * CC;
            float rv[RR];
            #pragma unroll
            for (int x = 0; x < RR; x++) rv[x] = v[rowb + (size_t)x * CC];
            if (dz == 1) {
                #pragma unroll
                for (int x = 0; x < RR; x++)
                    g_vh[rowb + (size_t)x * CC] = __float2half_rn(rv[x]);
            }
            #pragma unroll
            for (int dy = 0; dy < 3; dy++) {
                const float w0 = wr[dz * 9 + dy * 3 + 0];
                const float w1 = wr[dz * 9 + dy * 3 + 1];
                const float w2 = wr[dz * 9 + dy * 3 + 2];
                float* t = (dy == 0) ? t0 : (dy == 1) ? t1 : t2;
                #pragma unroll
                for (int x = 0; x < RR; x++) {
                    float acc = w1 * rv[x];
                    if (x > 0)      acc += w0 * rv[x - 1];
                    if (x < RR - 1) acc += w2 * rv[x + 1];
                    t[x] += acc;
                }
            }
        }

        if (yy > 0) {
            const size_t ob = zb + (size_t)((yy - 1) * RR) * CC;
            #pragma unroll
            for (int x = 0; x < RR; x++)
                g_lepe[ob + (size_t)x * CC] = A[x] + t2[x];
        }
        #pragma unroll
        for (int x = 0; x < RR; x++) {
            A[x]  = Bc[x] + t1[x];
            Bc[x] = bv + t0[x];
        }
    }
    const size_t ob = zb + (size_t)((RR - 1) * RR) * CC;
    #pragma unroll
    for (int x = 0; x < RR; x++)
        g_lepe[ob + (size_t)x * CC] = A[x];
}

__device__ __forceinline__ uint32_t smem_u32(const void* p) {
    uint32_t a;
    asm("{ .reg .u64 t; cvta.to.shared.u64 t, %1; cvt.u32.u64 %0, t; }" : "=r"(a) : "l"(p));
    return a;
}
__device__ __forceinline__ void ldsm4(uint32_t* r, uint32_t addr) {
    asm volatile("ldmatrix.sync.aligned.m8n8.x4.shared.b16 {%0,%1,%2,%3}, [%4];"
                 : "=r"(r[0]), "=r"(r[1]), "=r"(r[2]), "=r"(r[3]) : "r"(addr));
}
__device__ __forceinline__ void ldsm4t(uint32_t* r, uint32_t addr) {
    asm volatile("ldmatrix.sync.aligned.m8n8.x4.trans.shared.b16 {%0,%1,%2,%3}, [%4];"
                 : "=r"(r[0]), "=r"(r[1]), "=r"(r[2]), "=r"(r[3]) : "r"(addr));
}
__device__ __forceinline__ void mma16816(float* d, const uint32_t* a, const uint32_t* b) {
    asm volatile("mma.sync.aligned.m16n8k16.row.col.f32.f16.f16.f32 "
                 "{%0,%1,%2,%3}, {%4,%5,%6,%7}, {%8,%9}, {%0,%1,%2,%3};"
                 : "+f"(d[0]), "+f"(d[1]), "+f"(d[2]), "+f"(d[3])
                 : "r"(a[0]), "r"(a[1]), "r"(a[2]), "r"(a[3]), "r"(b[0]), "r"(b[1]));
}
__device__ __forceinline__ uint32_t exp2_pack(float lo, float hi) {
    __half2 h = __floats2half2_rn(lo, hi);
    uint32_t r;
    asm("ex2.approx.f16x2 %0, %1;" : "=r"(r) : "r"(*(uint32_t*)&h));
    return r;
}
__device__ __forceinline__ void cpa16(uint32_t dst, const void* src) {
    asm volatile("cp.async.cg.shared.global [%0], [%1], 16;" :: "r"(dst), "l"(src));
}
#define CPA_COMMIT() asm volatile("cp.async.commit_group;" ::: "memory")
#define CPA_WAIT(n)  asm volatile("cp.async.wait_group %0;" :: "n"(n) : "memory")

__device__ __forceinline__ void stage_kv(uint32_t kd, uint32_t vd,
                                         const __half* __restrict__ kh,
                                         const __half* __restrict__ vh,
                                         int l0, int tid) {
    for (int i = tid; i < 512; i += NT) {
        const int r = i >> 3, ch = i & 7;
        const size_t g = (size_t)(l0 + r) * CC + ch * 8;
        cpa16(kd + r * 144 + ch * 16, kh + g);
        cpa16(vd + r * 144 + ch * 16, vh + g);
    }
}

__global__ void __launch_bounds__(NT, 4) attn_kernel(float* __restrict__ out) {
    extern __shared__ __align__(16) char dsm[];
    __shared__ float Ls[BM];
    float* Os = (float*)dsm;

    const int tid  = threadIdx.x;
    const int lane = tid & 31;
    const int wm   = tid >> 5;
    const int b    = blockIdx.y / NH;
    const int h    = blockIdx.y % NH;
    const int row0 = blockIdx.x * BM;

    const __half* qh = g_qh + (size_t)b * LL * CC + h * HD;
    const __half* kh = g_kh + (size_t)b * LL * CC + h * HD;
    const __half* vh = g_vh + (size_t)b * LL * CC + h * HD;

    const uint32_t qsm = smem_u32(dsm);
    const uint32_t ksm = qsm + QB;
    const uint32_t vsm = qsm + QB + 2 * TILE;

    #pragma unroll
    for (int p = 0; p < 8; p++) {
        const int i = tid + p * NT;
        const int r = i >> 3, ch = i & 7;
        cpa16(qsm + r * 144 + ch * 16, qh + (size_t)(row0 + r) * CC + ch * 8);
    }
    stage_kv(ksm, vsm, kh, vh, 0, tid);
    CPA_COMMIT();
    CPA_WAIT(0);
    __syncthreads();

    const int arow = lane & 15;
    const int acol = (lane >> 4) * 8;
    const int frow = ((lane >> 4) & 1) * 8 + (lane & 7);
    const int fcol = ((lane >> 3) & 1) * 8;
    const int trow = lane & 15;
    const int tcol = ((lane >> 4) & 1) * 8;

    uint32_t aq[2][4][4];
    #pragma unroll
    for (int mt = 0; mt < 2; mt++)
        #pragma unroll
        for (int kc = 0; kc < 4; kc++)
            ldsm4(aq[mt][kc],
                  qsm + (uint32_t)((wm * 32 + mt * 16 + arow) * QSTR + kc * 16 + acol) * 2);

    float oacc[2][8][4];
    #pragma unroll
    for (int mt = 0; mt < 2; mt++)
        #pragma unroll
        for (int j = 0; j < 8; j++)
            #pragma unroll
            for (int e = 0; e < 4; e++) oacc[mt][j][e] = 0.f;
    float lsA[2] = {0.f, 0.f}, lsB[2] = {0.f, 0.f};

    for (int it = 0; it < NITER; it++) {
        const uint32_t kbase = ksm + (uint32_t)(it & 1) * TILE;
        const uint32_t vbase = vsm + (uint32_t)(it & 1) * TILE;

        if (it + 1 < NITER)
            stage_kv(ksm + ((it + 1) & 1) * TILE, vsm + ((it + 1) & 1) * TILE,
                     kh, vh, (it + 1) * BN, tid);
        CPA_COMMIT();

        #pragma unroll
        for (int nch = 0; nch < 2; nch++) {
            const int nb = nch * 32;

            float sacc[2][4][4];
            #pragma unroll
            for (int mt = 0; mt < 2; mt++)
                #pragma unroll
                for (int j = 0; j < 4; j++)
                    #pragma unroll
                    for (int e = 0; e < 4; e++) sacc[mt][j][e] = 0.f;

            #pragma unroll
            for (int j2 = 0; j2 < 2; j2++) {
                #pragma unroll
                for (int ks = 0; ks < 4; ks++) {
                    uint32_t kb[4];
                    ldsm4(kb, kbase + (uint32_t)((nb + j2 * 16 + frow) * QSTR + ks * 16 + fcol) * 2);
                    #pragma unroll
                    for (int mt = 0; mt < 2; mt++) {
                        mma16816(sacc[mt][2 * j2],     aq[mt][ks], kb);
                        mma16816(sacc[mt][2 * j2 + 1], aq[mt][ks], kb + 2);
                    }
                }
            }

            uint32_t pf[2][2][4];
            #pragma unroll
            for (int mt = 0; mt < 2; mt++) {
                __half2 hsA = __half2half2(__ushort_as_half(0));
                __half2 hsB = hsA;
                #pragma unroll
                for (int j = 0; j < 4; j++) {
                    const uint32_t pA = exp2_pack(sacc[mt][j][0], sacc[mt][j][1]);
                    const uint32_t pB = exp2_pack(sacc[mt][j][2], sacc[mt][j][3]);
                    hsA = __hadd2(hsA, *(const __half2*)&pA);
                    hsB = __hadd2(hsB, *(const __half2*)&pB);
                    const int s = j >> 1, o = (j & 1) * 2;
                    pf[mt][s][o]     = pA;
                    pf[mt][s][o + 1] = pB;
                }
                const float2 fA = __half22float2(hsA);
                const float2 fB = __half22float2(hsB);
                lsA[mt] += fA.x + fA.y;
                lsB[mt] += fB.x + fB.y;
            }

            #pragma unroll
            for (int j2 = 0; j2 < 4; j2++) {
                #pragma unroll
                for (int s = 0; s < 2; s++) {
                    uint32_t vb[4];
                    ldsm4t(vb, vbase + (uint32_t)((nb + s * 16 + trow) * QSTR + j2 * 16 + tcol) * 2);
                    #pragma unroll
                    for (int mt = 0; mt < 2; mt++) {
                        mma16816(oacc[mt][2 * j2],     pf[mt][s], vb);
                        mma16816(oacc[mt][2 * j2 + 1], pf[mt][s], vb + 2);
                    }
                }
            }
        }

        CPA_WAIT(0);
        __syncthreads();
    }

    #pragma unroll
    for (int mt = 0; mt < 2; mt++) {
        lsA[mt] += __shfl_xor_sync(0xFFFFFFFFu, lsA[mt], 1);
        lsA[mt] += __shfl_xor_sync(0xFFFFFFFFu, lsA[mt], 2);
        lsB[mt] += __shfl_xor_sync(0xFFFFFFFFu, lsB[mt], 1);
        lsB[mt] += __shfl_xor_sync(0xFFFFFFFFu, lsB[mt], 2);
    }
    if ((lane & 3) == 0) {
        #pragma unroll
        for (int mt = 0; mt < 2; mt++) {
            const int r = wm * 32 + mt * 16 + (lane >> 2);
            Ls[r]     = lsA[mt];
            Ls[r + 8] = lsB[mt];
        }
    }
    __syncthreads();

    const int rb = wm * 32 + (lane >> 2);
    const int cq = (lane & 3) * 2;
    #pragma unroll
    for (int mt = 0; mt < 2; mt++)
        #pragma unroll
        for (int j = 0; j < 8; j++) {
            *(float2*)(Os + (rb + mt * 16) * OSTR + j * 8 + cq) =
                make_float2(oacc[mt][j][0], oacc[mt][j][1]);
            *(float2*)(Os + (rb + mt * 16 + 8) * OSTR + j * 8 + cq) =
                make_float2(oacc[mt][j][2], oacc[mt][j][3]);
        }
    __syncthreads();

    #pragma unroll
    for (int p = 0; p < 16; p++) {
        const int i = tid + p * NT;
        const int rr = i >> 4, f4 = i & 15;
        const float inv = 1.f / Ls[rr];
        const size_t g = (size_t)b * LL * CC + (size_t)(row0 + rr) * CC + h * HD + f4 * 4;
        float4 ov = *(float4*)(Os + rr * OSTR + f4 * 4);
        const float4 l4 = *(const float4*)(g_lepe + g);
        ov.x = ov.x * inv + l4.x;
        ov.y = ov.y * inv + l4.y;
        ov.z = ov.z * inv + l4.z;
        ov.w = ov.w * inv + l4.w;
        *(float4*)(out + g) = ov;
    }
}

extern "C" void kernel_launch(void* const* d_in, const int* in_sizes, int n_in,
                              void* d_out, int out_size) {
    const float* qkv  = (const float*)d_in[0];
    const float* w    = (const float*)d_in[1];
    const float* bias = (const float*)d_in[2];
    float* out = (float*)d_out;

    cudaFuncSetAttribute(attn_kernel, cudaFuncAttributeMaxDynamicSharedMemorySize,
                         SMEM_TOTAL);

    convert_qk<<<(int)(BLC / 8 / 256), 256>>>(qkv);

    const size_t VOFF = 2 * BLC;
    dim3 lgrid(3 * RR, BB);
    lepe_kernel<<<lgrid, 256>>>(qkv + VOFF, w, bias);

    dim3 grid(LL / BM, BB * NH);
    attn_kernel<<<grid, NT, SMEM_TOTAL>>>(out);
}

// round 14
// speedup vs baseline: 1.4448x; 1.0273x over previous
#include <cuda_runtime.h>
#include <cuda_fp16.h>
#include <cstdint>

#define RR 12
#define LL 1728
#define CC 768
#define HD 64
#define NH 12
#define BB 4
#define BM 128           // query rows per CTA (grid.x = 14, last block clamped)
#define BN 64
#define NITER (LL / BN)  // 27
#define NT 128           // 4 warps -> all 4 SMSPs occupied (wid%4 mapping)
#define QSCALE (0.125f * 1.4426950408889634f)
#define QSTR 72
#define OSTR 68
#define QB   (BM * QSTR * 2)       // 18432
#define TILE (BN * QSTR * 2)       // 9216
#define SMEM_TOTAL (QB + 4 * TILE) // 55296 -> 3 CTAs/SM

#define BLC ((size_t)BB * LL * CC)

__device__ float  g_lepe[BLC];
__device__ __half g_qh[BLC];
__device__ __half g_kh[BLC];
__device__ __half g_vh[BLC];

// ---------------------------------------------------------------------------
// Convert Q (scaled by hd^-0.5 * log2e) and K to fp16.
// ---------------------------------------------------------------------------
__global__ void __launch_bounds__(256) convert_qk(const float* __restrict__ qkv) {
    const size_t i = ((size_t)blockIdx.x * 256 + threadIdx.x) * 8;
    const float4 a = *(const float4*)(qkv + i);
    const float4 b = *(const float4*)(qkv + i + 4);
    __half2 q0 = __floats2half2_rn(a.x * QSCALE, a.y * QSCALE);
    __half2 q1 = __floats2half2_rn(a.z * QSCALE, a.w * QSCALE);
    __half2 q2 = __floats2half2_rn(b.x * QSCALE, b.y * QSCALE);
    __half2 q3 = __floats2half2_rn(b.z * QSCALE, b.w * QSCALE);
    *(uint4*)(g_qh + i) = make_uint4(*(uint32_t*)&q0, *(uint32_t*)&q1,
                                     *(uint32_t*)&q2, *(uint32_t*)&q3);
    const float4 c = *(const float4*)(qkv + BLC + i);
    const float4 d = *(const float4*)(qkv + BLC + i + 4);
    __half2 k0 = __floats2half2_rn(c.x, c.y);
    __half2 k1 = __floats2half2_rn(c.z, c.w);
    __half2 k2 = __floats2half2_rn(d.x, d.y);
    __half2 k3 = __floats2half2_rn(d.z, d.w);
    *(uint4*)(g_kh + i) = make_uint4(*(uint32_t*)&k0, *(uint32_t*)&k1,
                                     *(uint32_t*)&k2, *(uint32_t*)&k3);
}

// ---------------------------------------------------------------------------
// LePE depthwise 3x3x3, rolling-y (3x read amplification); fp16 V emit on the
// dz==1 row (each element exactly once).
// ---------------------------------------------------------------------------
__global__ void __launch_bounds__(256) lepe_kernel(const float* __restrict__ v,
                                                   const float* __restrict__ w,
                                                   const float* __restrict__ bias) {
    __shared__ float ws[256 * 27];
    const int bx   = blockIdx.x;          // 0..35
    const int cseg = bx % 3;
    const int z    = bx / 3;
    const int b    = blockIdx.y;
    const int c0   = cseg * 256;
    const int tid  = threadIdx.x;
    const int c    = c0 + tid;

    for (int i = tid; i < 256 * 27; i += 256) ws[i] = w[c0 * 27 + i];
    __syncthreads();
    float wr[27];
    #pragma unroll
    for (int i = 0; i < 27; i++) wr[i] = ws[tid * 27 + i];
    const float bv = bias[c];

    const size_t zb = ((size_t)b * LL + (size_t)z * RR * RR) * CC + c;
    const size_t zstep = (size_t)RR * RR * CC;

    float A[RR], Bc[RR];
    #pragma unroll
    for (int x = 0; x < RR; x++) { A[x] = bv; Bc[x] = bv; }

    for (int yy = 0; yy < RR; yy++) {
        float t0[RR], t1[RR], t2[RR];
        #pragma unroll
        for (int x = 0; x < RR; x++) { t0[x] = 0.f; t1[x] = 0.f; t2[x] = 0.f; }

        #pragma unroll
        for (int dz = 0; dz < 3; dz++) {
            const int zz = z + dz - 1;
            if ((unsigned)zz >= RR) continue;
            const size_t rowb = zb + (size_t)(dz - 1) * zstep + (size_t)(yy * RR) * CC;
            float rv[RR];
            #pragma unroll
            for (int x = 0; x < RR; x++) rv[x] = v[rowb + (size_t)x * CC];
            if (dz == 1) {
                #pragma unroll
                for (int x = 0; x < RR; x++)
                    g_vh[rowb + (size_t)x * CC] = __float2half_rn(rv[x]);
            }
            #pragma unroll
            for (int dy = 0; dy < 3; dy++) {
                const float w0 = wr[dz * 9 + dy * 3 + 0];
                const float w1 = wr[dz * 9 + dy * 3 + 1];
                const float w2 = wr[dz * 9 + dy * 3 + 2];
                float* t = (dy == 0) ? t0 : (dy == 1) ? t1 : t2;
                #pragma unroll
                for (int x = 0; x < RR; x++) {
                    float acc = w1 * rv[x];
                    if (x > 0)      acc += w0 * rv[x - 1];
                    if (x < RR - 1) acc += w2 * rv[x + 1];
                    t[x] += acc;
                }
            }
        }

        if (yy > 0) {
            const size_t ob = zb + (size_t)((yy - 1) * RR) * CC;
            #pragma unroll
            for (int x = 0; x < RR; x++)
                g_lepe[ob + (size_t)x * CC] = A[x] + t2[x];
        }
        #pragma unroll
        for (int x = 0; x < RR; x++) {
            A[x]  = Bc[x] + t1[x];
            Bc[x] = bv + t0[x];
        }
    }
    const size_t ob = zb + (size_t)((RR - 1) * RR) * CC;
    #pragma unroll
    for (int x = 0; x < RR; x++)
        g_lepe[ob + (size_t)x * CC] = A[x];
}

// ---------------------------------------------------------------------------
// mma / cp.async helpers
// ---------------------------------------------------------------------------
__device__ __forceinline__ uint32_t smem_u32(const void* p) {
    uint32_t a;
    asm("{ .reg .u64 t; cvta.to.shared.u64 t, %1; cvt.u32.u64 %0, t; }" : "=r"(a) : "l"(p));
    return a;
}
__device__ __forceinline__ void ldsm4(uint32_t* r, uint32_t addr) {
    asm volatile("ldmatrix.sync.aligned.m8n8.x4.shared.b16 {%0,%1,%2,%3}, [%4];"
                 : "=r"(r[0]), "=r"(r[1]), "=r"(r[2]), "=r"(r[3]) : "r"(addr));
}
__device__ __forceinline__ void ldsm4t(uint32_t* r, uint32_t addr) {
    asm volatile("ldmatrix.sync.aligned.m8n8.x4.trans.shared.b16 {%0,%1,%2,%3}, [%4];"
                 : "=r"(r[0]), "=r"(r[1]), "=r"(r[2]), "=r"(r[3]) : "r"(addr));
}
__device__ __forceinline__ void mma16816(float* d, const uint32_t* a, const uint32_t* b) {
    asm volatile("mma.sync.aligned.m16n8k16.row.col.f32.f16.f16.f32 "
                 "{%0,%1,%2,%3}, {%4,%5,%6,%7}, {%8,%9}, {%0,%1,%2,%3};"
                 : "+f"(d[0]), "+f"(d[1]), "+f"(d[2]), "+f"(d[3])
                 : "r"(a[0]), "r"(a[1]), "r"(a[2]), "r"(a[3]), "r"(b[0]), "r"(b[1]));
}
__device__ __forceinline__ uint32_t exp2_pack(float lo, float hi) {
    __half2 h = __floats2half2_rn(lo, hi);
    uint32_t r;
    asm("ex2.approx.f16x2 %0, %1;" : "=r"(r) : "r"(*(uint32_t*)&h));
    return r;
}
__device__ __forceinline__ void cpa16(uint32_t dst, const void* src) {
    asm volatile("cp.async.cg.shared.global [%0], [%1], 16;" :: "r"(dst), "l"(src));
}
#define CPA_COMMIT() asm volatile("cp.async.commit_group;" ::: "memory")
#define CPA_WAIT(n)  asm volatile("cp.async.wait_group %0;" :: "n"(n) : "memory")

// stage one 64-key fp16 K/V tile via cp.async (128 threads: 4 chunks/thread/tensor)
__device__ __forceinline__ void stage_kv(uint32_t kd, uint32_t vd,
                                         const __half* __restrict__ kh,
                                         const __half* __restrict__ vh,
                                         int l0, int tid) {
    #pragma unroll
    for (int p = 0; p < 4; p++) {
        const int i = tid + p * NT;
        const int r = i >> 3, ch = i & 7;
        const size_t g = (size_t)(l0 + r) * CC + ch * 8;
        cpa16(kd + r * 144 + ch * 16, kh + g);
        cpa16(vd + r * 144 + ch * 16, vh + g);
    }
}

// ---------------------------------------------------------------------------
// fp16 HMMA flash attention. CTA = 128 threads = 4 independent warps (one per
// SMSP), each owning 32 query rows vs all keys. Double-buffered cp.async ring.
// ---------------------------------------------------------------------------
__global__ void __launch_bounds__(NT, 3) attn_kernel(float* __restrict__ out) {
    extern __shared__ __align__(16) char dsm[];
    __shared__ float Ls[BM];
    float* Os = (float*)dsm;

    const int tid  = threadIdx.x;
    const int lane = tid & 31;
    const int wm   = tid >> 5;    // warp = M quarter (32 rows)
    const int b    = blockIdx.y / NH;
    const int h    = blockIdx.y % NH;
    const int row0 = blockIdx.x * BM;

    const __half* qh = g_qh + (size_t)b * LL * CC + h * HD;
    const __half* kh = g_kh + (size_t)b * LL * CC + h * HD;
    const __half* vh = g_vh + (size_t)b * LL * CC + h * HD;

    const uint32_t qsm = smem_u32(dsm);
    const uint32_t ksm = qsm + QB;
    const uint32_t vsm = qsm + QB + 2 * TILE;

    // --- prologue: async-stage Q (rows clamped for the 14th block), tile0 ---
    #pragma unroll
    for (int p = 0; p < 8; p++) {
        const int i = tid + p * NT;
        const int r = i >> 3, ch = i & 7;
        const int rq = (row0 + r < LL) ? (row0 + r) : (LL - 1);
        cpa16(qsm + r * 144 + ch * 16, qh + (size_t)rq * CC + ch * 8);
    }
    stage_kv(ksm, vsm, kh, vh, 0, tid);
    CPA_COMMIT();
    CPA_WAIT(0);
    __syncthreads();

    const int arow = lane & 15;
    const int acol = (lane >> 4) * 8;
    const int frow = ((lane >> 4) & 1) * 8 + (lane & 7);
    const int fcol = ((lane >> 3) & 1) * 8;
    const int trow = lane & 15;
    const int tcol = ((lane >> 4) & 1) * 8;

    uint32_t aq[2][4][4];
    #pragma unroll
    for (int mt = 0; mt < 2; mt++)
        #pragma unroll
        for (int kc = 0; kc < 4; kc++)
            ldsm4(aq[mt][kc],
                  qsm + (uint32_t)((wm * 32 + mt * 16 + arow) * QSTR + kc * 16 + acol) * 2);

    float oacc[2][8][4];
    #pragma unroll
    for (int mt = 0; mt < 2; mt++)
        #pragma unroll
        for (int j = 0; j < 8; j++)
            #pragma unroll
            for (int e = 0; e < 4; e++) oacc[mt][j][e] = 0.f;
    float lsA[2] = {0.f, 0.f}, lsB[2] = {0.f, 0.f};

    for (int it = 0; it < NITER; it++) {
        const uint32_t kbase = ksm + (uint32_t)(it & 1) * TILE;
        const uint32_t vbase = vsm + (uint32_t)(it & 1) * TILE;

        if (it + 1 < NITER)
            stage_kv(ksm + ((it + 1) & 1) * TILE, vsm + ((it + 1) & 1) * TILE,
                     kh, vh, (it + 1) * BN, tid);
        CPA_COMMIT();

        #pragma unroll
        for (int nch = 0; nch < 2; nch++) {
            const int nb = nch * 32;

            float sacc[2][4][4];
            #pragma unroll
            for (int mt = 0; mt < 2; mt++)
                #pragma unroll
                for (int j = 0; j < 4; j++)
                    #pragma unroll
                    for (int e = 0; e < 4; e++) sacc[mt][j][e] = 0.f;

            #pragma unroll
            for (int j2 = 0; j2 < 2; j2++) {
                #pragma unroll
                for (int ks = 0; ks < 4; ks++) {
                    uint32_t kb[4];
                    ldsm4(kb, kbase + (uint32_t)((nb + j2 * 16 + frow) * QSTR + ks * 16 + fcol) * 2);
                    #pragma unroll
                    for (int mt = 0; mt < 2; mt++) {
                        mma16816(sacc[mt][2 * j2],     aq[mt][ks], kb);
                        mma16816(sacc[mt][2 * j2 + 1], aq[mt][ks], kb + 2);
                    }
                }
            }

            uint32_t pf[2][2][4];
            #pragma unroll
            for (int mt = 0; mt < 2; mt++) {
                __half2 hsA = __half2half2(__ushort_as_half(0));
                __half2 hsB = hsA;
                #pragma unroll
                for (int j = 0; j < 4; j++) {
                    const uint32_t pA = exp2_pack(sacc[mt][j][0], sacc[mt][j][1]);
                    const uint32_t pB = exp2_pack(sacc[mt][j][2], sacc[mt][j][3]);
                    hsA = __hadd2(hsA, *(const __half2*)&pA);
                    hsB = __hadd2(hsB, *(const __half2*)&pB);
                    const int s = j >> 1, o = (j & 1) * 2;
                    pf[mt][s][o]     = pA;
                    pf[mt][s][o + 1] = pB;
                }
                const float2 fA = __half22float2(hsA);
                const float2 fB = __half22float2(hsB);
                lsA[mt] += fA.x + fA.y;
                lsB[mt] += fB.x + fB.y;
            }

            #pragma unroll
            for (int j2 = 0; j2 < 4; j2++) {
                #pragma unroll
                for (int s = 0; s < 2; s++) {
                    uint32_t vb[4];
                    ldsm4t(vb, vbase + (uint32_t)((nb + s * 16 + trow) * QSTR + j2 * 16 + tcol) * 2);
                    #pragma unroll
                    for (int mt = 0; mt < 2; mt++) {
                        mma16816(oacc[mt][2 * j2],     pf[mt][s], vb);
                        mma16816(oacc[mt][2 * j2 + 1], pf[mt][s], vb + 2);
                    }
                }
            }
        }

        CPA_WAIT(0);
        __syncthreads();
    }

    // --- row sums (quad reduce, rows private to warp) ---
    #pragma unroll
    for (int mt = 0; mt < 2; mt++) {
        lsA[mt] += __shfl_xor_sync(0xFFFFFFFFu, lsA[mt], 1);
        lsA[mt] += __shfl_xor_sync(0xFFFFFFFFu, lsA[mt], 2);
        lsB[mt] += __shfl_xor_sync(0xFFFFFFFFu, lsB[mt], 1);
        lsB[mt] += __shfl_xor_sync(0xFFFFFFFFu, lsB[mt], 2);
    }
    if ((lane & 3) == 0) {
        #pragma unroll
        for (int mt = 0; mt < 2; mt++) {
            const int r = wm * 32 + mt * 16 + (lane >> 2);
            Ls[r]     = lsA[mt];
            Ls[r + 8] = lsB[mt];
        }
    }
    __syncthreads();   // done with K/V smem; Os may overlay

    // --- stage O through smem ---
    const int rb = wm * 32 + (lane >> 2);
    const int cq = (lane & 3) * 2;
    #pragma unroll
    for (int mt = 0; mt < 2; mt++)
        #pragma unroll
        for (int j = 0; j < 8; j++) {
            *(float2*)(Os + (rb + mt * 16) * OSTR + j * 8 + cq) =
                make_float2(oacc[mt][j][0], oacc[mt][j][1]);
            *(float2*)(Os + (rb + mt * 16 + 8) * OSTR + j * 8 + cq) =
                make_float2(oacc[mt][j][2], oacc[mt][j][3]);
        }
    __syncthreads();

    // --- coalesced store: O/lsum + lepe (guarded for the 14th block) ---
    #pragma unroll
    for (int p = 0; p < 16; p++) {
        const int i = tid + p * NT;
        const int rr = i >> 4, f4 = i & 15;
        const int grow = row0 + rr;
        if (grow < LL) {
            const float inv = 1.f / Ls[rr];
            const size_t g = (size_t)b * LL * CC + (size_t)grow * CC + h * HD + f4 * 4;
            float4 ov = *(float4*)(Os + rr * OSTR + f4 * 4);
            const float4 l4 = *(const float4*)(g_lepe + g);
            ov.x = ov.x * inv + l4.x;
            ov.y = ov.y * inv + l4.y;
            ov.z = ov.z * inv + l4.z;
            ov.w = ov.w * inv + l4.w;
            *(float4*)(out + g) = ov;
        }
    }
}

extern "C" void kernel_launch(void* const* d_in, const int* in_sizes, int n_in,
                              void* d_out, int out_size) {
    const float* qkv  = (const float*)d_in[0];
    const float* w    = (const float*)d_in[1];
    const float* bias = (const float*)d_in[2];
    float* out = (float*)d_out;

    cudaFuncSetAttribute(attn_kernel, cudaFuncAttributeMaxDynamicSharedMemorySize,
                         SMEM_TOTAL);

    convert_qk<<<(int)(BLC / 8 / 256), 256>>>(qkv);

    const size_t VOFF = 2 * BLC;
    dim3 lgrid(3 * RR, BB);
    lepe_kernel<<<lgrid, 256>>>(qkv + VOFF, w, bias);

    dim3 grid((LL + BM - 1) / BM, BB * NH);
    attn_kernel<<<grid, NT, SMEM_TOTAL>>>(out);
}